// round 1
// baseline (speedup 1.0000x reference)
#include <cuda_runtime.h>
#include <math.h>

#define BATCH 32
#define NROI 1000
#define NCLS 81
#define MAXI 100
#define PAD 1024
#define NTHREADS 1024

__global__ __launch_bounds__(NTHREADS)
void detection_layer_kernel(const float* __restrict__ rois,
                            const float* __restrict__ probs,
                            const float* __restrict__ bbox,
                            const float* __restrict__ std_dev,
                            float* __restrict__ out)
{
    __shared__ float s_box[NROI * 4];
    __shared__ float s_score[NROI];
    __shared__ short s_cls[NROI];
    __shared__ float s_key[PAD];
    __shared__ short s_sidx[PAD];
    __shared__ unsigned char s_keep[PAD];
    __shared__ float s_out[MAXI * 6];
    __shared__ int s_cnt;

    const int b = blockIdx.x;
    const int t = threadIdx.x;

    if (t == 0) s_cnt = 0;
    s_key[t] = -INFINITY;
    s_sidx[t] = (short)t;          // pads: distinct indices, -inf keys
    // zero the output staging buffer early
    for (int o = t; o < MAXI * 6; o += NTHREADS) s_out[o] = 0.0f;
    __syncthreads();

    // ---------- Phase 1: per-ROI argmax, delta apply, clip, validity ----------
    if (t < NROI) {
        const float* p = probs + (size_t)(b * NROI + t) * NCLS;
        float best = p[0];
        int bi = 0;
        #pragma unroll 4
        for (int c = 1; c < NCLS; ++c) {
            float v = p[c];
            if (v > best) { best = v; bi = c; }   // strict > == first-max (jnp.argmax)
        }
        const float* dv = bbox + ((size_t)(b * NROI + t) * NCLS + bi) * 4;
        float d0 = dv[0] * std_dev[0];
        float d1 = dv[1] * std_dev[1];
        float d2 = dv[2] * std_dev[2];
        float d3 = dv[3] * std_dev[3];

        const float* r = rois + (size_t)(b * NROI + t) * 4;
        float y1 = r[0], x1 = r[1], y2 = r[2], x2 = r[3];
        float h = y2 - y1;
        float w = x2 - x1;
        float cy = y1 + 0.5f * h + d0 * h;
        float cx = x1 + 0.5f * w + d1 * w;
        h = h * expf(d2);
        w = w * expf(d3);
        float ny1 = cy - 0.5f * h;
        float nx1 = cx - 0.5f * w;
        float ny2 = ny1 + h;
        float nx2 = nx1 + w;
        // clip to window (0,0,1,1)
        ny1 = fminf(fmaxf(ny1, 0.0f), 1.0f);
        nx1 = fminf(fmaxf(nx1, 0.0f), 1.0f);
        ny2 = fminf(fmaxf(ny2, 0.0f), 1.0f);
        nx2 = fminf(fmaxf(nx2, 0.0f), 1.0f);

        s_box[t * 4 + 0] = ny1;
        s_box[t * 4 + 1] = nx1;
        s_box[t * 4 + 2] = ny2;
        s_box[t * 4 + 3] = nx2;
        s_score[t] = best;
        s_cls[t] = (short)bi;

        bool valid = (bi > 0) && (best >= 0.7f);
        if (valid) {
            int pos = atomicAdd(&s_cnt, 1);
            s_key[pos] = best;
            s_sidx[pos] = (short)t;
        }
    }
    __syncthreads();
    const int M = s_cnt;

    // ---------- Phase 2: bitonic sort of PAD slots, desc score / asc index ----------
    for (int k = 2; k <= PAD; k <<= 1) {
        for (int j = k >> 1; j > 0; j >>= 1) {
            __syncthreads();
            int ixj = t ^ j;
            if (ixj > t) {
                float ka = s_key[t];   short ia = s_sidx[t];
                float kb = s_key[ixj]; short ib = s_sidx[ixj];
                // "b should come before a" under (score desc, index asc)
                bool b_before_a = (kb > ka) || (kb == ka && ib < ia);
                bool dir = ((t & k) == 0);        // true: this segment sorted "ascending" (our order)
                bool sw = dir ? b_before_a : !b_before_a;
                if (sw) {
                    s_key[t] = kb;  s_sidx[t] = ib;
                    s_key[ixj] = ka; s_sidx[ixj] = ia;
                }
            }
        }
    }
    __syncthreads();

    // ---------- Phase 3: greedy class-aware NMS over the M valid entries ----------
    s_keep[t] = (t < M) ? (unsigned char)1 : (unsigned char)0;
    __syncthreads();

    for (int i = 0; i < M; ++i) {
        if (s_keep[i]) {                    // uniform read across block
            int oi = s_sidx[i];
            float iy1 = s_box[oi * 4 + 0];
            float ix1 = s_box[oi * 4 + 1];
            float iy2 = s_box[oi * 4 + 2];
            float ix2 = s_box[oi * 4 + 3];
            short ic = s_cls[oi];
            float ai = (iy2 - iy1) * (ix2 - ix1);
            for (int jj = i + 1 + t; jj < M; jj += NTHREADS) {
                if (!s_keep[jj]) continue;
                int oj = s_sidx[jj];
                if (s_cls[oj] != ic) continue;
                float jy1 = s_box[oj * 4 + 0];
                float jx1 = s_box[oj * 4 + 1];
                float jy2 = s_box[oj * 4 + 2];
                float jx2 = s_box[oj * 4 + 3];
                float aj = (jy2 - jy1) * (jx2 - jx1);
                float ih = fmaxf(fminf(iy2, jy2) - fmaxf(iy1, jy1), 0.0f);
                float iw = fmaxf(fminf(ix2, jx2) - fmaxf(ix1, jx1), 0.0f);
                float inter = ih * iw;
                float uni = ai + aj - inter;
                float iou = inter / fmaxf(uni, 1e-8f);
                if (iou > 0.3f) s_keep[jj] = 0;
            }
        }
        __syncthreads();
    }

    // ---------- Phase 4: compact kept rows (sorted order) into staging, write out ----------
    if (t == 0) {
        int cnt = 0;
        for (int r2 = 0; r2 < M && cnt < MAXI; ++r2) {
            if (s_keep[r2]) {
                int o = s_sidx[r2];
                s_out[cnt * 6 + 0] = s_box[o * 4 + 0];
                s_out[cnt * 6 + 1] = s_box[o * 4 + 1];
                s_out[cnt * 6 + 2] = s_box[o * 4 + 2];
                s_out[cnt * 6 + 3] = s_box[o * 4 + 3];
                s_out[cnt * 6 + 4] = (float)s_cls[o];
                s_out[cnt * 6 + 5] = s_score[o];
                ++cnt;
            }
        }
    }
    __syncthreads();

    float* ob = out + (size_t)b * MAXI * 6;
    for (int o = t; o < MAXI * 6; o += NTHREADS) ob[o] = s_out[o];
}

extern "C" void kernel_launch(void* const* d_in, const int* in_sizes, int n_in,
                              void* d_out, int out_size)
{
    const float* rois    = (const float*)d_in[0];
    const float* probs   = (const float*)d_in[1];
    const float* bbox    = (const float*)d_in[2];
    const float* std_dev = (const float*)d_in[3];
    float* out = (float*)d_out;
    detection_layer_kernel<<<BATCH, NTHREADS>>>(rois, probs, bbox, std_dev, out);
}

// round 2
// speedup vs baseline: 2.3805x; 2.3805x over previous
#include <cuda_runtime.h>
#include <math.h>

#define BATCH 32
#define NROI 1000
#define NCLS 81
#define MAXI 100
#define NTOT (BATCH * NROI)

// scratch (device globals — no allocation allowed)
__device__ float4 g_box[NTOT];
__device__ float2 g_meta[NTOT];   // {score, class}

// ---------------------------------------------------------------------------
// Kernel A: warp-per-ROI argmax over 81 classes (coalesced), delta apply, clip
// ---------------------------------------------------------------------------
__global__ __launch_bounds__(256)
void detA_kernel(const float* __restrict__ rois,
                 const float* __restrict__ probs,
                 const float* __restrict__ bbox,
                 const float* __restrict__ std_dev)
{
    const int warp = (blockIdx.x * 256 + threadIdx.x) >> 5;
    const int lane = threadIdx.x & 31;
    if (warp >= NTOT) return;

    const float* p = probs + (size_t)warp * NCLS;
    // coalesced: lanes read consecutive addresses
    float v0 = p[lane];
    float v1 = p[lane + 32];
    float v2 = (lane < NCLS - 64) ? p[lane + 64] : -INFINITY;

    float best = v0; int bi = lane;
    if (v1 > best) { best = v1; bi = lane + 32; }
    if (v2 > best) { best = v2; bi = lane + 64; }

    // warp reduce: max value, ties -> smaller class index (first-max semantics)
    #pragma unroll
    for (int off = 16; off > 0; off >>= 1) {
        float ov = __shfl_down_sync(0xffffffffu, best, off);
        int   oi = __shfl_down_sync(0xffffffffu, bi,   off);
        if (ov > best || (ov == best && oi < bi)) { best = ov; bi = oi; }
    }

    if (lane == 0) {
        const float4 sd = *(const float4*)std_dev;
        const float4 dv = *(const float4*)(bbox + ((size_t)warp * NCLS + bi) * 4);
        const float4 r  = *(const float4*)(rois + (size_t)warp * 4);

        float d0 = dv.x * sd.x, d1 = dv.y * sd.y, d2 = dv.z * sd.z, d3 = dv.w * sd.w;
        float h = r.z - r.x;
        float w = r.w - r.y;
        float cy = r.x + 0.5f * h + d0 * h;
        float cx = r.y + 0.5f * w + d1 * w;
        h *= expf(d2);
        w *= expf(d3);
        float ny1 = cy - 0.5f * h;
        float nx1 = cx - 0.5f * w;
        float ny2 = ny1 + h;
        float nx2 = nx1 + w;
        ny1 = fminf(fmaxf(ny1, 0.0f), 1.0f);
        nx1 = fminf(fmaxf(nx1, 0.0f), 1.0f);
        ny2 = fminf(fmaxf(ny2, 0.0f), 1.0f);
        nx2 = fminf(fmaxf(nx2, 0.0f), 1.0f);

        g_box[warp]  = make_float4(ny1, nx1, ny2, nx2);
        g_meta[warp] = make_float2(best, (float)bi);
    }
}

// ---------------------------------------------------------------------------
// Kernel B: per-image compact -> rank sort -> per-class greedy NMS -> emit
// ---------------------------------------------------------------------------
__global__ __launch_bounds__(1024)
void detB_kernel(float* __restrict__ out)
{
    __shared__ float  s_cscore[NROI];
    __shared__ short  s_cidx[NROI];
    __shared__ short  s_ccls[NROI];
    __shared__ float  s_sbox[NROI * 4];   // sorted boxes
    __shared__ float  s_sscore[NROI];     // sorted scores
    __shared__ short  s_scls[NROI];       // sorted classes
    __shared__ short  s_bucket[NROI];     // class-grouped sorted positions
    __shared__ unsigned char s_keep[NROI];
    __shared__ int    s_ccount[NCLS];
    __shared__ int    s_cstart[NCLS];
    __shared__ float  s_out[MAXI * 6];
    __shared__ int    s_cnt;

    const int b = blockIdx.x;
    const int t = threadIdx.x;
    const int base = b * NROI;

    if (t == 0) s_cnt = 0;
    if (t < NCLS) s_ccount[t] = 0;
    for (int o = t; o < MAXI * 6; o += 1024) s_out[o] = 0.0f;

    // ---- load meta, compact valid entries ----
    float myscore = 0.0f; int mycls = 0;
    if (t < NROI) {
        float2 m = g_meta[base + t];
        myscore = m.x;
        mycls = (int)m.y;
    }
    __syncthreads();
    if (t < NROI && mycls > 0 && myscore >= 0.7f) {
        int pos = atomicAdd(&s_cnt, 1);
        s_cscore[pos] = myscore;
        s_cidx[pos]   = (short)t;
        s_ccls[pos]   = (short)mycls;
    }
    __syncthreads();
    const int M = s_cnt;

    // ---- rank sort: (score desc, original index asc) ----
    int rank = 0;
    float ks = 0.0f; short ki = 0; short kc = 0;
    if (t < M) {
        ks = s_cscore[t]; ki = s_cidx[t]; kc = s_ccls[t];
        for (int j = 0; j < M; ++j) {
            float js = s_cscore[j];
            rank += (js > ks) || (js == ks && s_cidx[j] < ki);
        }
    }
    __syncthreads();   // done reading compaction arrays
    if (t < M) {
        float4 bx = g_box[base + ki];
        s_sbox[rank * 4 + 0] = bx.x;
        s_sbox[rank * 4 + 1] = bx.y;
        s_sbox[rank * 4 + 2] = bx.z;
        s_sbox[rank * 4 + 3] = bx.w;
        s_sscore[rank] = ks;
        s_scls[rank]   = kc;
        s_keep[rank]   = 1;
        atomicAdd(&s_ccount[kc], 1);
    }
    __syncthreads();

    // ---- class bucket starts (81 threads, tiny loops) ----
    if (t < NCLS) {
        int st = 0;
        for (int c = 0; c < t; ++c) st += s_ccount[c];
        s_cstart[t] = st;
    }
    __syncthreads();

    // ---- counting-sort entries into class buckets (preserve sorted order) ----
    if (t < M) {
        short myc = s_scls[t];
        int w = 0;
        for (int j = 0; j < t; ++j) w += (s_scls[j] == myc);
        s_bucket[s_cstart[myc] + w] = (short)t;
    }
    __syncthreads();

    // ---- per-class greedy NMS (classes independent: sup requires same class) ----
    if (t < NCLS) {
        int st = s_cstart[t];
        int cnt = s_ccount[t];
        for (int a = 1; a < cnt; ++a) {
            int pa = s_bucket[st + a];
            float ay1 = s_sbox[pa * 4 + 0];
            float ax1 = s_sbox[pa * 4 + 1];
            float ay2 = s_sbox[pa * 4 + 2];
            float ax2 = s_sbox[pa * 4 + 3];
            float aa = (ay2 - ay1) * (ax2 - ax1);
            for (int q = 0; q < a; ++q) {
                int pb = s_bucket[st + q];
                if (!s_keep[pb]) continue;
                float by1 = s_sbox[pb * 4 + 0];
                float bx1 = s_sbox[pb * 4 + 1];
                float by2 = s_sbox[pb * 4 + 2];
                float bx2 = s_sbox[pb * 4 + 3];
                float ab = (by2 - by1) * (bx2 - bx1);
                float ih = fmaxf(fminf(ay2, by2) - fmaxf(ay1, by1), 0.0f);
                float iw = fmaxf(fminf(ax2, bx2) - fmaxf(ax1, bx1), 0.0f);
                float inter = ih * iw;
                float iou = inter / fmaxf(aa + ab - inter, 1e-8f);
                if (iou > 0.3f) { s_keep[pa] = 0; break; }
            }
        }
    }
    __syncthreads();

    // ---- slot assignment: count kept entries before me ----
    if (t < M && s_keep[t]) {
        int slot = 0;
        for (int j = 0; j < t; ++j) slot += s_keep[j];
        if (slot < MAXI) {
            s_out[slot * 6 + 0] = s_sbox[t * 4 + 0];
            s_out[slot * 6 + 1] = s_sbox[t * 4 + 1];
            s_out[slot * 6 + 2] = s_sbox[t * 4 + 2];
            s_out[slot * 6 + 3] = s_sbox[t * 4 + 3];
            s_out[slot * 6 + 4] = (float)s_scls[t];
            s_out[slot * 6 + 5] = s_sscore[t];
        }
    }
    __syncthreads();

    float* ob = out + (size_t)b * MAXI * 6;
    for (int o = t; o < MAXI * 6; o += 1024) ob[o] = s_out[o];
}

extern "C" void kernel_launch(void* const* d_in, const int* in_sizes, int n_in,
                              void* d_out, int out_size)
{
    const float* rois    = (const float*)d_in[0];
    const float* probs   = (const float*)d_in[1];
    const float* bbox    = (const float*)d_in[2];
    const float* std_dev = (const float*)d_in[3];
    float* out = (float*)d_out;

    const int warps_total = NTOT;                  // one warp per ROI
    const int blocksA = (warps_total * 32 + 255) / 256;
    detA_kernel<<<blocksA, 256>>>(rois, probs, bbox, std_dev);
    detB_kernel<<<BATCH, 1024>>>(out);
}

// round 3
// speedup vs baseline: 2.4527x; 1.0303x over previous
#include <cuda_runtime.h>
#include <math.h>

#define BATCH 32
#define NROI 1000
#define NCLS 81
#define MAXI 100
#define NTOT (BATCH * NROI)
#define RPW 4                      // ROIs per warp in kernel A

// scratch (device globals — no allocation allowed)
__device__ float4 g_box[NTOT];
__device__ float2 g_meta[NTOT];   // {score, class}

// ---------------------------------------------------------------------------
// Kernel A: warp handles 4 ROIs; coalesced argmax over 81 classes, 4-way ILP
// ---------------------------------------------------------------------------
__global__ __launch_bounds__(256)
void detA_kernel(const float* __restrict__ rois,
                 const float* __restrict__ probs,
                 const float* __restrict__ bbox,
                 const float* __restrict__ std_dev)
{
    const int warp = (blockIdx.x * 256 + threadIdx.x) >> 5;
    const int lane = threadIdx.x & 31;
    const int r0 = warp * RPW;
    if (r0 >= NTOT) return;

    float best[RPW];
    int   bi[RPW];

    // issue all loads up front (12 independent LDGs)
    #pragma unroll
    for (int k = 0; k < RPW; ++k) {
        const float* p = probs + (size_t)(r0 + k) * NCLS;
        float v0 = p[lane];
        float v1 = p[lane + 32];
        float v2 = (lane < NCLS - 64) ? p[lane + 64] : -INFINITY;
        best[k] = v0; bi[k] = lane;
        if (v1 > best[k]) { best[k] = v1; bi[k] = lane + 32; }
        if (v2 > best[k]) { best[k] = v2; bi[k] = lane + 64; }
    }

    // 4 interleaved butterfly reductions (independent chains -> pipelined)
    #pragma unroll
    for (int off = 16; off > 0; off >>= 1) {
        #pragma unroll
        for (int k = 0; k < RPW; ++k) {
            float ov = __shfl_down_sync(0xffffffffu, best[k], off);
            int   oi = __shfl_down_sync(0xffffffffu, bi[k],   off);
            if (ov > best[k] || (ov == best[k] && oi < bi[k])) { best[k] = ov; bi[k] = oi; }
        }
    }

    if (lane == 0) {
        const float4 sd = *(const float4*)std_dev;
        #pragma unroll
        for (int k = 0; k < RPW; ++k) {
            const int ri = r0 + k;
            const float4 dv = *(const float4*)(bbox + ((size_t)ri * NCLS + bi[k]) * 4);
            const float4 r  = *(const float4*)(rois + (size_t)ri * 4);

            float d0 = dv.x * sd.x, d1 = dv.y * sd.y, d2 = dv.z * sd.z, d3 = dv.w * sd.w;
            float h = r.z - r.x;
            float w = r.w - r.y;
            float cy = r.x + 0.5f * h + d0 * h;
            float cx = r.y + 0.5f * w + d1 * w;
            h *= expf(d2);
            w *= expf(d3);
            float ny1 = cy - 0.5f * h;
            float nx1 = cx - 0.5f * w;
            float ny2 = ny1 + h;
            float nx2 = nx1 + w;
            ny1 = fminf(fmaxf(ny1, 0.0f), 1.0f);
            nx1 = fminf(fmaxf(nx1, 0.0f), 1.0f);
            ny2 = fminf(fmaxf(ny2, 0.0f), 1.0f);
            nx2 = fminf(fmaxf(nx2, 0.0f), 1.0f);

            g_box[ri]  = make_float4(ny1, nx1, ny2, nx2);
            g_meta[ri] = make_float2(best[k], (float)bi[k]);
        }
    }
}

// ---------------------------------------------------------------------------
// Kernel B: compact -> rank sort -> class buckets -> WARP-per-class NMS -> emit
// ---------------------------------------------------------------------------
__global__ __launch_bounds__(1024)
void detB_kernel(float* __restrict__ out)
{
    __shared__ float  s_cscore[NROI];
    __shared__ short  s_cidx[NROI];
    __shared__ short  s_ccls[NROI];
    __shared__ float  s_sbox[NROI * 4];
    __shared__ float  s_sscore[NROI];
    __shared__ short  s_scls[NROI];
    __shared__ short  s_bucket[NROI];
    __shared__ unsigned char s_keep[NROI];
    __shared__ int    s_ccount[NCLS];
    __shared__ int    s_cstart[NCLS];
    __shared__ float  s_out[MAXI * 6];
    __shared__ int    s_cnt;

    const int b = blockIdx.x;
    const int t = threadIdx.x;
    const int warpId = t >> 5;
    const int lane = t & 31;
    const int base = b * NROI;

    if (t == 0) s_cnt = 0;
    if (t < NCLS) s_ccount[t] = 0;
    for (int o = t; o < MAXI * 6; o += 1024) s_out[o] = 0.0f;

    // ---- load meta, compact valid entries ----
    float myscore = 0.0f; int mycls = 0;
    if (t < NROI) {
        float2 m = g_meta[base + t];
        myscore = m.x;
        mycls = (int)m.y;
    }
    __syncthreads();
    if (t < NROI && mycls > 0 && myscore >= 0.7f) {
        int pos = atomicAdd(&s_cnt, 1);
        s_cscore[pos] = myscore;
        s_cidx[pos]   = (short)t;
        s_ccls[pos]   = (short)mycls;
    }
    __syncthreads();
    const int M = s_cnt;

    // ---- rank sort: (score desc, original index asc) ----
    int rank = 0;
    float ks = 0.0f; short ki = 0; short kc = 0;
    if (t < M) {
        ks = s_cscore[t]; ki = s_cidx[t]; kc = s_ccls[t];
        for (int j = 0; j < M; ++j) {
            float js = s_cscore[j];
            rank += (js > ks) || (js == ks && s_cidx[j] < ki);
        }
    }
    __syncthreads();
    if (t < M) {
        float4 bx = g_box[base + ki];
        s_sbox[rank * 4 + 0] = bx.x;
        s_sbox[rank * 4 + 1] = bx.y;
        s_sbox[rank * 4 + 2] = bx.z;
        s_sbox[rank * 4 + 3] = bx.w;
        s_sscore[rank] = ks;
        s_scls[rank]   = kc;
        s_keep[rank]   = 1;
        atomicAdd(&s_ccount[kc], 1);
    }
    __syncthreads();

    // ---- class bucket starts ----
    if (t < NCLS) {
        int st = 0;
        for (int c = 0; c < t; ++c) st += s_ccount[c];
        s_cstart[t] = st;
    }
    __syncthreads();

    // ---- counting-sort into class buckets (preserves score order) ----
    if (t < M) {
        short myc = s_scls[t];
        int w = 0;
        for (int j = 0; j < t; ++j) w += (s_scls[j] == myc);
        s_bucket[s_cstart[myc] + w] = (short)t;
    }
    __syncthreads();

    // ---- warp-per-class greedy NMS (lanes parallelize predecessor tests) ----
    for (int c = warpId; c < NCLS; c += 32) {
        const int st  = s_cstart[c];
        const int cnt = s_ccount[c];
        for (int a = 1; a < cnt; ++a) {
            int pa = s_bucket[st + a];
            float ay1 = s_sbox[pa * 4 + 0];   // broadcast LDS (conflict-free)
            float ax1 = s_sbox[pa * 4 + 1];
            float ay2 = s_sbox[pa * 4 + 2];
            float ax2 = s_sbox[pa * 4 + 3];
            float aa = (ay2 - ay1) * (ax2 - ax1);
            bool hit = false;
            for (int q = lane; q < a; q += 32) {
                int pb = s_bucket[st + q];
                if (s_keep[pb]) {
                    float by1 = s_sbox[pb * 4 + 0];
                    float bx1 = s_sbox[pb * 4 + 1];
                    float by2 = s_sbox[pb * 4 + 2];
                    float bx2 = s_sbox[pb * 4 + 3];
                    float ab = (by2 - by1) * (bx2 - bx1);
                    float ih = fmaxf(fminf(ay2, by2) - fmaxf(ay1, by1), 0.0f);
                    float iw = fmaxf(fminf(ax2, bx2) - fmaxf(ax1, bx1), 0.0f);
                    float inter = ih * iw;
                    float iou = inter / fmaxf(aa + ab - inter, 1e-8f);
                    if (iou > 0.3f) hit = true;
                }
            }
            unsigned m = __ballot_sync(0xffffffffu, hit);
            if (m && lane == 0) s_keep[pa] = 0;
            __syncwarp();
        }
    }
    __syncthreads();

    // ---- slot assignment & staged output ----
    if (t < M && s_keep[t]) {
        int slot = 0;
        for (int j = 0; j < t; ++j) slot += s_keep[j];
        if (slot < MAXI) {
            s_out[slot * 6 + 0] = s_sbox[t * 4 + 0];
            s_out[slot * 6 + 1] = s_sbox[t * 4 + 1];
            s_out[slot * 6 + 2] = s_sbox[t * 4 + 2];
            s_out[slot * 6 + 3] = s_sbox[t * 4 + 3];
            s_out[slot * 6 + 4] = (float)s_scls[t];
            s_out[slot * 6 + 5] = s_sscore[t];
        }
    }
    __syncthreads();

    float* ob = out + (size_t)b * MAXI * 6;
    for (int o = t; o < MAXI * 6; o += 1024) ob[o] = s_out[o];
}

extern "C" void kernel_launch(void* const* d_in, const int* in_sizes, int n_in,
                              void* d_out, int out_size)
{
    const float* rois    = (const float*)d_in[0];
    const float* probs   = (const float*)d_in[1];
    const float* bbox    = (const float*)d_in[2];
    const float* std_dev = (const float*)d_in[3];
    float* out = (float*)d_out;

    const int warpsA  = NTOT / RPW;                       // 8000 warps
    const int blocksA = (warpsA * 32 + 255) / 256;        // 1000 blocks
    detA_kernel<<<blocksA, 256>>>(rois, probs, bbox, std_dev);
    detB_kernel<<<BATCH, 1024>>>(out);
}